// round 7
// baseline (speedup 1.0000x reference)
#include <cuda_runtime.h>
#include <cuda_bf16.h>
#include <cstdint>
#include <math.h>

#define T_TOK 16384
#define HDIM  2048
#define FDIM  256
#define NEXP  12
#define CAP   1707
#define CAPP  1792   // 14 * 128
#define LG2T  14

// ---------------- scratch (device globals; no allocs allowed) ----------------
__device__ float g_rw [T_TOK * 2];
__device__ int   g_sel[T_TOK * 2];
__device__ int   g_tok[NEXP * CAPP];
__device__ float g_wgt[NEXP * CAPP];
__device__ int   g_cnt[NEXP];
__device__ __align__(16) uint32_t g_h  [NEXP * CAPP * FDIM];      // tf32 intermediate
__device__ __align__(16) uint32_t g_w1t[NEXP * FDIM * HDIM];      // tf32 weights
__device__ __align__(16) uint32_t g_w2t[NEXP * HDIM * FDIM];
__device__ __align__(16) uint32_t g_w3t[NEXP * FDIM * HDIM];

// ---------------- helpers ----------------
__device__ __forceinline__ uint32_t f2tf(float f) {
    uint32_t u;
    asm("cvt.rna.tf32.f32 %0, %1;" : "=r"(u) : "f"(f));
    return u;
}

__device__ __forceinline__ void mma_tf32(float& d0, float& d1, float& d2, float& d3,
                                         uint32_t a0, uint32_t a1, uint32_t a2, uint32_t a3,
                                         uint32_t b0, uint32_t b1) {
    asm volatile(
        "mma.sync.aligned.m16n8k8.row.col.f32.tf32.tf32.f32 "
        "{%0,%1,%2,%3}, {%4,%5,%6,%7}, {%8,%9}, {%0,%1,%2,%3};"
        : "+f"(d0), "+f"(d1), "+f"(d2), "+f"(d3)
        : "r"(a0), "r"(a1), "r"(a2), "r"(a3), "r"(b0), "r"(b1));
}

__device__ __forceinline__ uint32_t sptr(const void* p) {
    return (uint32_t)__cvta_generic_to_shared(p);
}

#define CP16(dst_u32, src_ptr) \
    asm volatile("cp.async.cg.shared.global [%0], [%1], 16;" :: "r"(dst_u32), "l"(src_ptr))
#define CP_COMMIT() asm volatile("cp.async.commit_group;")
#define CP_WAIT1()  asm volatile("cp.async.wait_group 1;")

// ---------------- kernel 0: zero output ----------------
__global__ void k_zero(float4* out, int n4) {
    int i = blockIdx.x * blockDim.x + threadIdx.x;
    if (i < n4) out[i] = make_float4(0.f, 0.f, 0.f, 0.f);
}

// ---------------- kernel 0b: convert one weight tensor fp32 -> tf32 ----------------
__global__ void k_cvt(const float4* __restrict__ src, uint4* __restrict__ dst, int n4) {
    int i = blockIdx.x * blockDim.x + threadIdx.x;
    if (i < n4) {
        float4 v = src[i];
        uint4 u;
        u.x = f2tf(v.x); u.y = f2tf(v.y); u.z = f2tf(v.z); u.w = f2tf(v.w);
        dst[i] = u;
    }
}

// ---------------- kernel 1: gating (one warp per token) ----------------
__global__ __launch_bounds__(256) void k_gate(const float* __restrict__ x,
                                              const float* __restrict__ gw) {
    int warp = (blockIdx.x * blockDim.x + threadIdx.x) >> 5;
    int lane = threadIdx.x & 31;
    if (warp >= T_TOK) return;
    const float4* xr = (const float4*)(x + (size_t)warp * HDIM);

    float acc[NEXP];
#pragma unroll
    for (int e = 0; e < NEXP; e++) acc[e] = 0.f;
    for (int h4 = lane; h4 < HDIM / 4; h4 += 32) {
        float4 xv = xr[h4];
#pragma unroll
        for (int e = 0; e < NEXP; e++) {
            float4 gv = ((const float4*)(gw + e * HDIM))[h4];
            acc[e] += xv.x * gv.x + xv.y * gv.y + xv.z * gv.z + xv.w * gv.w;
        }
    }
#pragma unroll
    for (int e = 0; e < NEXP; e++) {
#pragma unroll
        for (int off = 16; off; off >>= 1)
            acc[e] += __shfl_xor_sync(0xffffffffu, acc[e], off);
    }
    if (lane == 0) {
        float m1 = -1e30f, m2 = -1e30f;
        int i1 = 0, i2 = 0;
#pragma unroll
        for (int e = 0; e < NEXP; e++) {
            float v = acc[e];
            if (v > m1)      { m2 = m1; i2 = i1; m1 = v; i1 = e; }
            else if (v > m2) { m2 = v;  i2 = e; }
        }
        float w1v = 1.f / (1.f + expf(m2 - m1));
        g_sel[warp * 2 + 0] = i1;
        g_sel[warp * 2 + 1] = i2;
        g_rw [warp * 2 + 0] = w1v;
        g_rw [warp * 2 + 1] = 1.f - w1v;
    }
}

// ---------------- kernel 2: order-preserving dispatch scan ----------------
__global__ __launch_bounds__(1024) void k_scan() {
    __shared__ int s[1024 * NEXP];
    int j = threadIdx.x;
    for (int i = j; i < NEXP * CAPP; i += 1024) { g_tok[i] = 0; g_wgt[i] = 0.f; }

    int base = j * 32;
    int myexp[32];
    int cnt[NEXP];
#pragma unroll
    for (int e = 0; e < NEXP; e++) cnt[e] = 0;
#pragma unroll
    for (int q = 0; q < 32; q++) {
        int i = base + q;
        int t = i & (T_TOK - 1);
        int k = i >> LG2T;
        int e = g_sel[t * 2 + k];
        myexp[q] = e;
#pragma unroll
        for (int ee = 0; ee < NEXP; ee++) cnt[ee] += (ee == e);
    }
    int run[NEXP];
#pragma unroll
    for (int e = 0; e < NEXP; e++) { run[e] = cnt[e]; s[j * NEXP + e] = run[e]; }
    __syncthreads();
    for (int d = 1; d < 1024; d <<= 1) {
        int tmp[NEXP];
#pragma unroll
        for (int e = 0; e < NEXP; e++) tmp[e] = (j >= d) ? s[(j - d) * NEXP + e] : 0;
        __syncthreads();
#pragma unroll
        for (int e = 0; e < NEXP; e++) { run[e] += tmp[e]; s[j * NEXP + e] = run[e]; }
        __syncthreads();
    }
    if (j == 1023) {
#pragma unroll
        for (int e = 0; e < NEXP; e++) g_cnt[e] = run[e];
    }
    int off[NEXP];
#pragma unroll
    for (int e = 0; e < NEXP; e++) off[e] = run[e] - cnt[e];
#pragma unroll
    for (int q = 0; q < 32; q++) {
        int i = base + q;
        int t = i & (T_TOK - 1);
        int k = i >> LG2T;
        int e = myexp[q];
        int pos = 0;
#pragma unroll
        for (int ee = 0; ee < NEXP; ee++)
            if (ee == e) { pos = off[ee]; off[ee]++; }
        if (pos < CAP) {
            g_tok[e * CAPP + pos] = t;
            g_wgt[e * CAPP + pos] = g_rw[t * 2 + k];
        }
    }
}

// ---------------- kernel 3: GEMM1 — 3-buffer ring, 1 sync/tile, prefetch-first ----------------
#define F1_AST 4608            // 128*36 uint32
#define F1_BST 4608            // 2*64*36
#define F1_STG (F1_AST + F1_BST)
#define F1_SMEM (3 * F1_STG * 4)

__global__ __launch_bounds__(128, 2) void k_ffn1(const float* __restrict__ x) {
    extern __shared__ uint32_t sm[];
    __shared__ int s_tok[128];

    int e    = blockIdx.z;
    int row0 = blockIdx.x * 128;
    int n0   = blockIdx.y * 64;
    int ne   = min(g_cnt[e], CAP);
    if (row0 >= ne) return;   // ffn2 skips the same tiles
    uint32_t* hout = g_h + (size_t)e * CAPP * FDIM;

    int tid = threadIdx.x;
    s_tok[tid] = g_tok[e * CAPP + row0 + tid];
    __syncthreads();

    const uint32_t* w1e = g_w1t + (size_t)e * FDIM * HDIM;
    const uint32_t* w3e = g_w3t + (size_t)e * FDIM * HDIM;

    int a_row[8], a_c4[8];
    const uint32_t* b_src[8];
    uint32_t a_dst[8], b_dst[8];
#pragma unroll
    for (int u = 0; u < 8; u++) {
        int idx = tid + 128 * u;
        a_row[u] = idx >> 3;
        a_c4 [u] = idx & 7;
        a_dst[u] = sptr(sm + a_row[u] * 36 + a_c4[u] * 4);
        int m = idx >> 9, rem = idx & 511;     // m: 0 = w1, 1 = w3
        int n = rem >> 3, c4 = rem & 7;
        b_src[u] = ((m == 0) ? w1e : w3e) + (size_t)(n0 + n) * HDIM + c4 * 4;
        b_dst[u] = sptr(sm + F1_AST + (m * 64 + n) * 36 + c4 * 4);
    }

    int warp = tid >> 5, lane = tid & 31;
    int wm = warp >> 1, wn = warp & 1;          // 2x2 warps, warp tile 64(M) x 32(N)
    int g = lane >> 2, tg = lane & 3;

    float accA[4][4][4], accB[4][4][4];
#pragma unroll
    for (int mi = 0; mi < 4; mi++)
#pragma unroll
        for (int ni = 0; ni < 4; ni++)
#pragma unroll
            for (int q = 0; q < 4; q++) { accA[mi][ni][q] = 0.f; accB[mi][ni][q] = 0.f; }

    // prologue: stage tiles 0,1 (buffers 0,1)
#pragma unroll
    for (int t = 0; t < 2; t++) {
        int k0 = t * 32;
        uint32_t off = t * F1_STG * 4;
#pragma unroll
        for (int u = 0; u < 8; u++) {
            CP16(a_dst[u] + off, x + (size_t)s_tok[a_row[u]] * HDIM + k0 + a_c4[u] * 4);
            CP16(b_dst[u] + off, b_src[u] + k0);
        }
        CP_COMMIT();
    }

    const int NT = HDIM / 32;
#pragma unroll 1
    for (int t = 0; t < NT; t++) {
        CP_WAIT1();               // tile t resident (t+1 may still be in flight)
        __syncthreads();          // also proves buffer (t+2)%3 was fully consumed at t-1

        // prefetch tile t+2 BEFORE compute
        int tn = t + 2;
        if (tn < NT) {
            int k0 = tn * 32;
            uint32_t off = (uint32_t)(tn % 3) * F1_STG * 4;
#pragma unroll
            for (int u = 0; u < 8; u++) {
                CP16(a_dst[u] + off, x + (size_t)s_tok[a_row[u]] * HDIM + k0 + a_c4[u] * 4);
                CP16(b_dst[u] + off, b_src[u] + k0);
            }
        }
        CP_COMMIT();

        const uint32_t* As = sm + (t % 3) * F1_STG;
        const uint32_t* Bs = As + F1_AST;

#pragma unroll
        for (int kk = 0; kk < 4; kk++) {
            uint32_t a[4][4];
#pragma unroll
            for (int mi = 0; mi < 4; mi++) {
                int r = wm * 64 + mi * 16;
                a[mi][0] = f2tf(__uint_as_float(As[(r + g)     * 36 + kk * 8 + tg]));
                a[mi][1] = f2tf(__uint_as_float(As[(r + 8 + g) * 36 + kk * 8 + tg]));
                a[mi][2] = f2tf(__uint_as_float(As[(r + g)     * 36 + kk * 8 + tg + 4]));
                a[mi][3] = f2tf(__uint_as_float(As[(r + 8 + g) * 36 + kk * 8 + tg + 4]));
            }
#pragma unroll
            for (int ni = 0; ni < 4; ni++) {
                int n = wn * 32 + ni * 8 + g;
                uint32_t b0 = Bs[n * 36 + kk * 8 + tg];
                uint32_t b1 = Bs[n * 36 + kk * 8 + tg + 4];
                uint32_t c0 = Bs[(64 + n) * 36 + kk * 8 + tg];
                uint32_t c1 = Bs[(64 + n) * 36 + kk * 8 + tg + 4];
#pragma unroll
                for (int mi = 0; mi < 4; mi++) {
                    mma_tf32(accA[mi][ni][0], accA[mi][ni][1], accA[mi][ni][2], accA[mi][ni][3],
                             a[mi][0], a[mi][1], a[mi][2], a[mi][3], b0, b1);
                    mma_tf32(accB[mi][ni][0], accB[mi][ni][1], accB[mi][ni][2], accB[mi][ni][3],
                             a[mi][0], a[mi][1], a[mi][2], a[mi][3], c0, c1);
                }
            }
        }
    }

    // epilogue: h = silu(a*b) stored as tf32
#pragma unroll
    for (int mi = 0; mi < 4; mi++) {
#pragma unroll
        for (int ni = 0; ni < 4; ni++) {
            int rbase = row0 + wm * 64 + mi * 16 + g;
            int cbase = n0 + wn * 32 + ni * 8 + tg * 2;
#pragma unroll
            for (int h = 0; h < 2; h++) {
                int r = rbase + h * 8;
                float p0 = accA[mi][ni][h * 2 + 0] * accB[mi][ni][h * 2 + 0];
                float p1 = accA[mi][ni][h * 2 + 1] * accB[mi][ni][h * 2 + 1];
                float s0 = p0 / (1.f + expf(-p0));
                float s1 = p1 / (1.f + expf(-p1));
                hout[(size_t)r * FDIM + cbase]     = f2tf(s0);
                hout[(size_t)r * FDIM + cbase + 1] = f2tf(s1);
            }
        }
    }
}

// ---------------- kernel 4: GEMM2 — 3-buffer ring, 1 sync/tile + weighted scatter ----------------
#define F2_AST 4608            // 128*36
#define F2_BST 4608            // 128*36
#define F2_STG (F2_AST + F2_BST)
#define F2_SMEM (3 * F2_STG * 4)

__global__ __launch_bounds__(128, 2) void k_ffn2(float* __restrict__ out) {
    extern __shared__ uint32_t sm[];
    __shared__ int   s_tok[128];
    __shared__ float s_wgt[128];

    int e    = blockIdx.z;
    int row0 = blockIdx.x * 128;
    int n0   = blockIdx.y * 128;
    int ne   = min(g_cnt[e], CAP);
    if (row0 >= ne) return;

    int tid = threadIdx.x;
    s_tok[tid] = g_tok[e * CAPP + row0 + tid];
    s_wgt[tid] = g_wgt[e * CAPP + row0 + tid];
    __syncthreads();

    const uint32_t* hin = g_h   + (size_t)e * CAPP * FDIM;
    const uint32_t* w2e = g_w2t + (size_t)e * HDIM * FDIM;

    const uint32_t* a_src[8];
    uint32_t a_dst[8];
    const uint32_t* b_src[8];
    uint32_t b_dst[8];
#pragma unroll
    for (int u = 0; u < 8; u++) {
        int idx = tid + 128 * u;
        int row = idx >> 3, c4 = idx & 7;
        a_src[u] = hin + (size_t)(row0 + row) * FDIM + c4 * 4;
        a_dst[u] = sptr(sm + row * 36 + c4 * 4);
        b_src[u] = w2e + (size_t)(n0 + row) * FDIM + c4 * 4;
        b_dst[u] = sptr(sm + F2_AST + row * 36 + c4 * 4);
    }

    int warp = tid >> 5, lane = tid & 31;
    int wm = warp >> 1, wn = warp & 1;          // warp tile 64(M) x 64(N)
    int g = lane >> 2, tg = lane & 3;

    float acc[4][8][4];
#pragma unroll
    for (int mi = 0; mi < 4; mi++)
#pragma unroll
        for (int ni = 0; ni < 8; ni++)
#pragma unroll
            for (int q = 0; q < 4; q++) acc[mi][ni][q] = 0.f;

#pragma unroll
    for (int t = 0; t < 2; t++) {
        int k0 = t * 32;
        uint32_t off = t * F2_STG * 4;
#pragma unroll
        for (int u = 0; u < 8; u++) {
            CP16(a_dst[u] + off, a_src[u] + k0);
            CP16(b_dst[u] + off, b_src[u] + k0);
        }
        CP_COMMIT();
    }

    const int NT = FDIM / 32;
#pragma unroll 1
    for (int t = 0; t < NT; t++) {
        CP_WAIT1();
        __syncthreads();

        int tn = t + 2;
        if (tn < NT) {
            int k0 = tn * 32;
            uint32_t off = (uint32_t)(tn % 3) * F2_STG * 4;
#pragma unroll
            for (int u = 0; u < 8; u++) {
                CP16(a_dst[u] + off, a_src[u] + k0);
                CP16(b_dst[u] + off, b_src[u] + k0);
            }
        }
        CP_COMMIT();

        const uint32_t* As = sm + (t % 3) * F2_STG;
        const uint32_t* Bs = As + F2_AST;

#pragma unroll
        for (int kk = 0; kk < 4; kk++) {
            uint32_t a[4][4];
#pragma unroll
            for (int mi = 0; mi < 4; mi++) {
                int r = wm * 64 + mi * 16;
                a[mi][0] = As[(r + g)     * 36 + kk * 8 + tg];
                a[mi][1] = As[(r + 8 + g) * 36 + kk * 8 + tg];
                a[mi][2] = As[(r + g)     * 36 + kk * 8 + tg + 4];
                a[mi][3] = As[(r + 8 + g) * 36 + kk * 8 + tg + 4];
            }
#pragma unroll
            for (int ni = 0; ni < 8; ni++) {
                int n = wn * 64 + ni * 8 + g;
                uint32_t b0 = Bs[n * 36 + kk * 8 + tg];
                uint32_t b1 = Bs[n * 36 + kk * 8 + tg + 4];
#pragma unroll
                for (int mi = 0; mi < 4; mi++)
                    mma_tf32(acc[mi][ni][0], acc[mi][ni][1], acc[mi][ni][2], acc[mi][ni][3],
                             a[mi][0], a[mi][1], a[mi][2], a[mi][3], b0, b1);
            }
        }
    }

    // epilogue: weighted atomic scatter
#pragma unroll
    for (int mi = 0; mi < 4; mi++) {
#pragma unroll
        for (int ni = 0; ni < 8; ni++) {
            int cbase = n0 + wn * 64 + ni * 8 + tg * 2;
#pragma unroll
            for (int h = 0; h < 2; h++) {
                int rl = wm * 64 + mi * 16 + g + h * 8;
                float w = s_wgt[rl];
                if (w != 0.f) {
                    int tok = s_tok[rl];
                    atomicAdd(&out[(size_t)tok * HDIM + cbase],     acc[mi][ni][h * 2 + 0] * w);
                    atomicAdd(&out[(size_t)tok * HDIM + cbase + 1], acc[mi][ni][h * 2 + 1] * w);
                }
            }
        }
    }
}

// ---------------- launch ----------------
extern "C" void kernel_launch(void* const* d_in, const int* in_sizes, int n_in,
                              void* d_out, int out_size) {
    const float* x  = nullptr;
    const float* gw = nullptr;
    const float* wbig[3] = {nullptr, nullptr, nullptr};
    int nbig = 0;
    for (int i = 0; i < n_in; i++) {
        long long sz = in_sizes[i];
        if (sz == (long long)T_TOK * HDIM)      x = (const float*)d_in[i];
        else if (sz == (long long)NEXP * HDIM)  gw = (const float*)d_in[i];
        else if (nbig < 3)                      wbig[nbig++] = (const float*)d_in[i];
    }
    const float* w1 = wbig[0];
    const float* w2 = wbig[1];
    const float* w3 = wbig[2];
    float* out = (float*)d_out;

    cudaFuncSetAttribute(k_ffn1, cudaFuncAttributeMaxDynamicSharedMemorySize, F1_SMEM);
    cudaFuncSetAttribute(k_ffn2, cudaFuncAttributeMaxDynamicSharedMemorySize, F2_SMEM);

    uint32_t* w1t; cudaGetSymbolAddress((void**)&w1t, g_w1t);
    uint32_t* w2t; cudaGetSymbolAddress((void**)&w2t, g_w2t);
    uint32_t* w3t; cudaGetSymbolAddress((void**)&w3t, g_w3t);

    int wn4 = NEXP * FDIM * HDIM / 4;
    int n4 = T_TOK * HDIM / 4;

    // Order chosen so k_ffn1 is launch index 5 (ncu -s 5 -c 1 captures it).
    k_gate<<<T_TOK / 8, 256>>>(x, gw);                                          // 0
    k_cvt<<<(wn4 + 255) / 256, 256>>>((const float4*)w1, (uint4*)w1t, wn4);     // 1
    k_cvt<<<(wn4 + 255) / 256, 256>>>((const float4*)w3, (uint4*)w3t, wn4);     // 2
    k_scan<<<1, 1024>>>();                                                      // 3
    k_zero<<<(n4 + 255) / 256, 256>>>((float4*)out, n4);                        // 4
    k_ffn1<<<dim3(CAPP / 128, FDIM / 64, NEXP), 128, F1_SMEM>>>(x);             // 5 <- profiled
    k_cvt<<<(wn4 + 255) / 256, 256>>>((const float4*)w2, (uint4*)w2t, wn4);     // 6
    k_ffn2<<<dim3(CAPP / 128, HDIM / 128, NEXP), 128, F2_SMEM>>>(out);          // 7
}

// round 8
// speedup vs baseline: 1.1168x; 1.1168x over previous
#include <cuda_runtime.h>
#include <cuda_bf16.h>
#include <cstdint>
#include <math.h>

#define T_TOK 16384
#define HDIM  2048
#define FDIM  256
#define NEXP  12
#define CAP   1707
#define CAPP  1792   // 14 * 128
#define LG2T  14
#define SCAN_B 32
#define SCAN_T 256

// ---------------- scratch (device globals; no allocs allowed) ----------------
__device__ float g_rw [T_TOK * 2];
__device__ int   g_sel[T_TOK * 2];
__device__ int   g_tok[NEXP * CAPP];
__device__ float g_wgt[NEXP * CAPP];
__device__ int   g_cnt[NEXP];
__device__ int   g_agg[SCAN_B * NEXP];
__device__ int   g_readycnt;
__device__ __align__(16) uint32_t g_h  [NEXP * CAPP * FDIM];      // tf32 intermediate
__device__ __align__(16) uint32_t g_w1t[NEXP * FDIM * HDIM];      // tf32 weights
__device__ __align__(16) uint32_t g_w2t[NEXP * HDIM * FDIM];
__device__ __align__(16) uint32_t g_w3t[NEXP * FDIM * HDIM];

// ---------------- helpers ----------------
__device__ __forceinline__ uint32_t f2tf(float f) {
    uint32_t u;
    asm("cvt.rna.tf32.f32 %0, %1;" : "=r"(u) : "f"(f));
    return u;
}

__device__ __forceinline__ void mma_tf32(float& d0, float& d1, float& d2, float& d3,
                                         uint32_t a0, uint32_t a1, uint32_t a2, uint32_t a3,
                                         uint32_t b0, uint32_t b1) {
    asm volatile(
        "mma.sync.aligned.m16n8k8.row.col.f32.tf32.tf32.f32 "
        "{%0,%1,%2,%3}, {%4,%5,%6,%7}, {%8,%9}, {%0,%1,%2,%3};"
        : "+f"(d0), "+f"(d1), "+f"(d2), "+f"(d3)
        : "r"(a0), "r"(a1), "r"(a2), "r"(a3), "r"(b0), "r"(b1));
}

__device__ __forceinline__ uint32_t sptr(const void* p) {
    return (uint32_t)__cvta_generic_to_shared(p);
}

#define CP16(dst_u32, src_ptr) \
    asm volatile("cp.async.cg.shared.global [%0], [%1], 16;" :: "r"(dst_u32), "l"(src_ptr))
#define CP_COMMIT() asm volatile("cp.async.commit_group;")
#define CP_WAIT1()  asm volatile("cp.async.wait_group 1;")

// ---------------- kernel A: convert all three weight tensors fp32 -> tf32 ----------------
__global__ void k_cvt_all(const float4* __restrict__ s1, uint4* __restrict__ d1,
                          const float4* __restrict__ s2, uint4* __restrict__ d2,
                          const float4* __restrict__ s3, uint4* __restrict__ d3, int wn4) {
    int i = blockIdx.x * blockDim.x + threadIdx.x;
    const float4* s;
    uint4* d;
    int j;
    if (i < wn4)              { s = s1; d = d1; j = i; }
    else if (i < 2 * wn4)     { s = s2; d = d2; j = i - wn4; }
    else if (i < 3 * wn4)     { s = s3; d = d3; j = i - 2 * wn4; }
    else return;
    float4 v = s[j];
    uint4 u;
    u.x = f2tf(v.x); u.y = f2tf(v.y); u.z = f2tf(v.z); u.w = f2tf(v.w);
    d[j] = u;
}

// ---------------- kernel B: gating (one warp per token) + zero out ----------------
__global__ __launch_bounds__(256) void k_gate(const float* __restrict__ x,
                                              const float* __restrict__ gw,
                                              float4* __restrict__ out) {
    // reset scan flag (any block; cheap, idempotent within this launch)
    if (blockIdx.x == 0 && threadIdx.x == 0) g_readycnt = 0;

    // zero this block's 8 token rows of out: 8*2048 floats = 4096 float4
    {
        int base = blockIdx.x * 4096;
#pragma unroll
        for (int u = 0; u < 16; u++)
            out[base + threadIdx.x + 256 * u] = make_float4(0.f, 0.f, 0.f, 0.f);
    }

    int warp = (blockIdx.x * blockDim.x + threadIdx.x) >> 5;
    int lane = threadIdx.x & 31;
    if (warp >= T_TOK) return;
    const float4* xr = (const float4*)(x + (size_t)warp * HDIM);

    float acc[NEXP];
#pragma unroll
    for (int e = 0; e < NEXP; e++) acc[e] = 0.f;
    for (int h4 = lane; h4 < HDIM / 4; h4 += 32) {
        float4 xv = xr[h4];
#pragma unroll
        for (int e = 0; e < NEXP; e++) {
            float4 gv = ((const float4*)(gw + e * HDIM))[h4];
            acc[e] += xv.x * gv.x + xv.y * gv.y + xv.z * gv.z + xv.w * gv.w;
        }
    }
#pragma unroll
    for (int e = 0; e < NEXP; e++) {
#pragma unroll
        for (int off = 16; off; off >>= 1)
            acc[e] += __shfl_xor_sync(0xffffffffu, acc[e], off);
    }
    if (lane == 0) {
        float m1 = -1e30f, m2 = -1e30f;
        int i1 = 0, i2 = 0;
#pragma unroll
        for (int e = 0; e < NEXP; e++) {
            float v = acc[e];
            if (v > m1)      { m2 = m1; i2 = i1; m1 = v; i1 = e; }
            else if (v > m2) { m2 = v;  i2 = e; }
        }
        float w1v = 1.f / (1.f + expf(m2 - m1));
        g_sel[warp * 2 + 0] = i1;
        g_sel[warp * 2 + 1] = i2;
        g_rw [warp * 2 + 0] = w1v;
        g_rw [warp * 2 + 1] = 1.f - w1v;
    }
}

// ---------------- kernel C: parallel order-preserving dispatch scan ----------------
// 32 blocks x 256 thr. Entry i in [0,2T): t = i & (T-1), k = i >> 14, e = sel[t][k].
// Stable positions via ballot/popc (lane) + group/warp/block/global hierarchy.
__global__ __launch_bounds__(SCAN_T) void k_scan_par() {
    __shared__ int swcnt [8][NEXP];
    __shared__ int swbase[8][NEXP];
    __shared__ int sgbase[NEXP];
    __shared__ int sagg[SCAN_B * NEXP];

    int blk = blockIdx.x, tid = threadIdx.x, w = tid >> 5, lane = tid & 31;

    // clear this block's slice of the dispatch table (pad rows -> tok 0 / wgt 0)
    const int SLICE = (NEXP * CAPP) / SCAN_B;   // 672
    for (int i = tid; i < SLICE; i += SCAN_T) {
        int idx = blk * SLICE + i;
        g_tok[idx] = 0;
        g_wgt[idx] = 0.f;
    }

    // count phase: warp handles 4 consecutive 32-entry groups
    int base_i = blk * 1024 + w * 128;
    int myexp[4];
    int cnt[NEXP];
#pragma unroll
    for (int e = 0; e < NEXP; e++) cnt[e] = 0;
#pragma unroll
    for (int q = 0; q < 4; q++) {
        int i = base_i + q * 32 + lane;
        int t = i & (T_TOK - 1);
        int k = i >> LG2T;
        int e = g_sel[t * 2 + k];
        myexp[q] = e;
#pragma unroll
        for (int ee = 0; ee < NEXP; ee++) {
            unsigned m = __ballot_sync(0xffffffffu, e == ee);
            cnt[ee] += __popc(m);
        }
    }
    if (lane == 0) {
#pragma unroll
        for (int ee = 0; ee < NEXP; ee++) swcnt[w][ee] = cnt[ee];
    }
    __syncthreads();

    // per-warp exclusive bases within block; publish block aggregate
    if (tid < NEXP) {
        int run = 0;
#pragma unroll
        for (int ww = 0; ww < 8; ww++) { swbase[ww][tid] = run; run += swcnt[ww][tid]; }
        g_agg[blk * NEXP + tid] = run;
    }
    __syncthreads();
    if (tid == 0) {
        __threadfence();
        atomicAdd(&g_readycnt, 1);
        while (atomicAdd(&g_readycnt, 0) < SCAN_B) { }
    }
    __syncthreads();

    // gather all aggregates (L2 reads; producers fenced before flag)
    for (int i = tid; i < SCAN_B * NEXP; i += SCAN_T) sagg[i] = __ldcg(&g_agg[i]);
    __syncthreads();

    if (tid < NEXP) {
        int b = 0;
        for (int bb = 0; bb < blk; bb++) b += sagg[bb * NEXP + tid];
        sgbase[tid] = b;
        if (blk == 0) {
            int tot = 0;
            for (int bb = 0; bb < SCAN_B; bb++) tot += sagg[bb * NEXP + tid];
            g_cnt[tid] = tot;
        }
    }
    __syncthreads();

    // write phase: stable global position = global base + warp base + running + lane rank
    int run2[NEXP];
#pragma unroll
    for (int ee = 0; ee < NEXP; ee++) run2[ee] = sgbase[ee] + swbase[w][ee];
#pragma unroll
    for (int q = 0; q < 4; q++) {
        int i = base_i + q * 32 + lane;
        int t = i & (T_TOK - 1);
        int k = i >> LG2T;
        int e = myexp[q];
        int pos = 0;
        unsigned lt = (1u << lane) - 1u;
#pragma unroll
        for (int ee = 0; ee < NEXP; ee++) {
            unsigned m = __ballot_sync(0xffffffffu, e == ee);
            if (e == ee) pos = run2[ee] + __popc(m & lt);
            run2[ee] += __popc(m);
        }
        if (pos < CAP) {
            g_tok[e * CAPP + pos] = t;
            g_wgt[e * CAPP + pos] = g_rw[t * 2 + k];
        }
    }
}

// ---------------- kernel 3: GEMM1 — R6 structure (2-stage, wait1) ----------------
#define F1_AST 4608            // 128*36 uint32
#define F1_BST 4608            // 2*64*36
#define F1_STG (F1_AST + F1_BST)
#define F1_SMEM (2 * F1_STG * 4)

__global__ __launch_bounds__(128, 2) void k_ffn1(const float* __restrict__ x) {
    extern __shared__ uint32_t sm[];
    __shared__ int s_tok[128];

    int e    = blockIdx.z;
    int row0 = blockIdx.x * 128;
    int n0   = blockIdx.y * 64;
    int ne   = min(g_cnt[e], CAP);
    if (row0 >= ne) return;   // ffn2 skips the same tiles
    uint32_t* hout = g_h + (size_t)e * CAPP * FDIM;

    int tid = threadIdx.x;
    s_tok[tid] = g_tok[e * CAPP + row0 + tid];
    __syncthreads();

    const uint32_t* w1e = g_w1t + (size_t)e * FDIM * HDIM;
    const uint32_t* w3e = g_w3t + (size_t)e * FDIM * HDIM;

    int a_row[8], a_c4[8];
    const uint32_t* b_src[8];
    uint32_t a_dst[8], b_dst[8];
#pragma unroll
    for (int u = 0; u < 8; u++) {
        int idx = tid + 128 * u;
        a_row[u] = idx >> 3;
        a_c4 [u] = idx & 7;
        a_dst[u] = sptr(sm + a_row[u] * 36 + a_c4[u] * 4);
        int m = idx >> 9, rem = idx & 511;     // m: 0 = w1, 1 = w3
        int n = rem >> 3, c4 = rem & 7;
        b_src[u] = ((m == 0) ? w1e : w3e) + (size_t)(n0 + n) * HDIM + c4 * 4;
        b_dst[u] = sptr(sm + F1_AST + (m * 64 + n) * 36 + c4 * 4);
    }

    int warp = tid >> 5, lane = tid & 31;
    int wm = warp >> 1, wn = warp & 1;          // 2x2 warps, warp tile 64(M) x 32(N)
    int g = lane >> 2, tg = lane & 3;

    float accA[4][4][4], accB[4][4][4];
#pragma unroll
    for (int mi = 0; mi < 4; mi++)
#pragma unroll
        for (int ni = 0; ni < 4; ni++)
#pragma unroll
            for (int q = 0; q < 4; q++) { accA[mi][ni][q] = 0.f; accB[mi][ni][q] = 0.f; }

#pragma unroll
    for (int t = 0; t < 2; t++) {
        int k0 = t * 32;
        uint32_t off = t * F1_STG * 4;
#pragma unroll
        for (int u = 0; u < 8; u++) {
            CP16(a_dst[u] + off, x + (size_t)s_tok[a_row[u]] * HDIM + k0 + a_c4[u] * 4);
            CP16(b_dst[u] + off, b_src[u] + k0);
        }
        CP_COMMIT();
    }

    const int NT = HDIM / 32;
#pragma unroll 1
    for (int t = 0; t < NT; t++) {
        CP_WAIT1();
        __syncthreads();
        int p = t & 1;
        const uint32_t* As = sm + p * F1_STG;
        const uint32_t* Bs = As + F1_AST;

#pragma unroll
        for (int kk = 0; kk < 4; kk++) {
            uint32_t a[4][4];
#pragma unroll
            for (int mi = 0; mi < 4; mi++) {
                int r = wm * 64 + mi * 16;
                a[mi][0] = f2tf(__uint_as_float(As[(r + g)     * 36 + kk * 8 + tg]));
                a[mi][1] = f2tf(__uint_as_float(As[(r + 8 + g) * 36 + kk * 8 + tg]));
                a[mi][2] = f2tf(__uint_as_float(As[(r + g)     * 36 + kk * 8 + tg + 4]));
                a[mi][3] = f2tf(__uint_as_float(As[(r + 8 + g) * 36 + kk * 8 + tg + 4]));
            }
#pragma unroll
            for (int ni = 0; ni < 4; ni++) {
                int n = wn * 32 + ni * 8 + g;
                uint32_t b0 = Bs[n * 36 + kk * 8 + tg];
                uint32_t b1 = Bs[n * 36 + kk * 8 + tg + 4];
                uint32_t c0 = Bs[(64 + n) * 36 + kk * 8 + tg];
                uint32_t c1 = Bs[(64 + n) * 36 + kk * 8 + tg + 4];
#pragma unroll
                for (int mi = 0; mi < 4; mi++) {
                    mma_tf32(accA[mi][ni][0], accA[mi][ni][1], accA[mi][ni][2], accA[mi][ni][3],
                             a[mi][0], a[mi][1], a[mi][2], a[mi][3], b0, b1);
                    mma_tf32(accB[mi][ni][0], accB[mi][ni][1], accB[mi][ni][2], accB[mi][ni][3],
                             a[mi][0], a[mi][1], a[mi][2], a[mi][3], c0, c1);
                }
            }
        }
        __syncthreads();

        int tn = t + 2;
        if (tn < NT) {
            int k0 = tn * 32;
            uint32_t off = p * F1_STG * 4;
#pragma unroll
            for (int u = 0; u < 8; u++) {
                CP16(a_dst[u] + off, x + (size_t)s_tok[a_row[u]] * HDIM + k0 + a_c4[u] * 4);
                CP16(b_dst[u] + off, b_src[u] + k0);
            }
        }
        CP_COMMIT();
    }

    // epilogue: h = silu(a*b) stored as tf32
#pragma unroll
    for (int mi = 0; mi < 4; mi++) {
#pragma unroll
        for (int ni = 0; ni < 4; ni++) {
            int rbase = row0 + wm * 64 + mi * 16 + g;
            int cbase = n0 + wn * 32 + ni * 8 + tg * 2;
#pragma unroll
            for (int h = 0; h < 2; h++) {
                int r = rbase + h * 8;
                float p0 = accA[mi][ni][h * 2 + 0] * accB[mi][ni][h * 2 + 0];
                float p1 = accA[mi][ni][h * 2 + 1] * accB[mi][ni][h * 2 + 1];
                float s0 = p0 / (1.f + expf(-p0));
                float s1 = p1 / (1.f + expf(-p1));
                hout[(size_t)r * FDIM + cbase]     = f2tf(s0);
                hout[(size_t)r * FDIM + cbase + 1] = f2tf(s1);
            }
        }
    }
}

// ---------------- kernel 4: GEMM2 — R6 structure + weighted scatter ----------------
#define F2_AST 4608            // 128*36
#define F2_BST 4608            // 128*36
#define F2_STG (F2_AST + F2_BST)
#define F2_SMEM (2 * F2_STG * 4)

__global__ __launch_bounds__(128, 2) void k_ffn2(float* __restrict__ out) {
    extern __shared__ uint32_t sm[];
    __shared__ int   s_tok[128];
    __shared__ float s_wgt[128];

    int e    = blockIdx.z;
    int row0 = blockIdx.x * 128;
    int n0   = blockIdx.y * 128;
    int ne   = min(g_cnt[e], CAP);
    if (row0 >= ne) return;

    int tid = threadIdx.x;
    s_tok[tid] = g_tok[e * CAPP + row0 + tid];
    s_wgt[tid] = g_wgt[e * CAPP + row0 + tid];
    __syncthreads();

    const uint32_t* hin = g_h   + (size_t)e * CAPP * FDIM;
    const uint32_t* w2e = g_w2t + (size_t)e * HDIM * FDIM;

    const uint32_t* a_src[8];
    uint32_t a_dst[8];
    const uint32_t* b_src[8];
    uint32_t b_dst[8];
#pragma unroll
    for (int u = 0; u < 8; u++) {
        int idx = tid + 128 * u;
        int row = idx >> 3, c4 = idx & 7;
        a_src[u] = hin + (size_t)(row0 + row) * FDIM + c4 * 4;
        a_dst[u] = sptr(sm + row * 36 + c4 * 4);
        b_src[u] = w2e + (size_t)(n0 + row) * FDIM + c4 * 4;
        b_dst[u] = sptr(sm + F2_AST + row * 36 + c4 * 4);
    }

    int warp = tid >> 5, lane = tid & 31;
    int wm = warp >> 1, wn = warp & 1;          // warp tile 64(M) x 64(N)
    int g = lane >> 2, tg = lane & 3;

    float acc[4][8][4];
#pragma unroll
    for (int mi = 0; mi < 4; mi++)
#pragma unroll
        for (int ni = 0; ni < 8; ni++)
#pragma unroll
            for (int q = 0; q < 4; q++) acc[mi][ni][q] = 0.f;

#pragma unroll
    for (int t = 0; t < 2; t++) {
        int k0 = t * 32;
        uint32_t off = t * F2_STG * 4;
#pragma unroll
        for (int u = 0; u < 8; u++) {
            CP16(a_dst[u] + off, a_src[u] + k0);
            CP16(b_dst[u] + off, b_src[u] + k0);
        }
        CP_COMMIT();
    }

    const int NT = FDIM / 32;
#pragma unroll 1
    for (int t = 0; t < NT; t++) {
        CP_WAIT1();
        __syncthreads();
        int p = t & 1;
        const uint32_t* As = sm + p * F2_STG;
        const uint32_t* Bs = As + F2_AST;

#pragma unroll
        for (int kk = 0; kk < 4; kk++) {
            uint32_t a[4][4];
#pragma unroll
            for (int mi = 0; mi < 4; mi++) {
                int r = wm * 64 + mi * 16;
                a[mi][0] = As[(r + g)     * 36 + kk * 8 + tg];
                a[mi][1] = As[(r + 8 + g) * 36 + kk * 8 + tg];
                a[mi][2] = As[(r + g)     * 36 + kk * 8 + tg + 4];
                a[mi][3] = As[(r + 8 + g) * 36 + kk * 8 + tg + 4];
            }
#pragma unroll
            for (int ni = 0; ni < 8; ni++) {
                int n = wn * 64 + ni * 8 + g;
                uint32_t b0 = Bs[n * 36 + kk * 8 + tg];
                uint32_t b1 = Bs[n * 36 + kk * 8 + tg + 4];
#pragma unroll
                for (int mi = 0; mi < 4; mi++)
                    mma_tf32(acc[mi][ni][0], acc[mi][ni][1], acc[mi][ni][2], acc[mi][ni][3],
                             a[mi][0], a[mi][1], a[mi][2], a[mi][3], b0, b1);
            }
        }
        __syncthreads();

        int tn = t + 2;
        if (tn < NT) {
            int k0 = tn * 32;
            uint32_t off = p * F2_STG * 4;
#pragma unroll
            for (int u = 0; u < 8; u++) {
                CP16(a_dst[u] + off, a_src[u] + k0);
                CP16(b_dst[u] + off, b_src[u] + k0);
            }
        }
        CP_COMMIT();
    }

#pragma unroll
    for (int mi = 0; mi < 4; mi++) {
#pragma unroll
        for (int ni = 0; ni < 8; ni++) {
            int cbase = n0 + wn * 64 + ni * 8 + tg * 2;
#pragma unroll
            for (int h = 0; h < 2; h++) {
                int rl = wm * 64 + mi * 16 + g + h * 8;
                float w = s_wgt[rl];
                if (w != 0.f) {
                    int tok = s_tok[rl];
                    atomicAdd(&out[(size_t)tok * HDIM + cbase],     acc[mi][ni][h * 2 + 0] * w);
                    atomicAdd(&out[(size_t)tok * HDIM + cbase + 1], acc[mi][ni][h * 2 + 1] * w);
                }
            }
        }
    }
}

// ---------------- launch ----------------
extern "C" void kernel_launch(void* const* d_in, const int* in_sizes, int n_in,
                              void* d_out, int out_size) {
    const float* x  = nullptr;
    const float* gw = nullptr;
    const float* wbig[3] = {nullptr, nullptr, nullptr};
    int nbig = 0;
    for (int i = 0; i < n_in; i++) {
        long long sz = in_sizes[i];
        if (sz == (long long)T_TOK * HDIM)      x = (const float*)d_in[i];
        else if (sz == (long long)NEXP * HDIM)  gw = (const float*)d_in[i];
        else if (nbig < 3)                      wbig[nbig++] = (const float*)d_in[i];
    }
    const float* w1 = wbig[0];
    const float* w2 = wbig[1];
    const float* w3 = wbig[2];
    float* out = (float*)d_out;

    cudaFuncSetAttribute(k_ffn1, cudaFuncAttributeMaxDynamicSharedMemorySize, F1_SMEM);
    cudaFuncSetAttribute(k_ffn2, cudaFuncAttributeMaxDynamicSharedMemorySize, F2_SMEM);

    uint32_t* w1t; cudaGetSymbolAddress((void**)&w1t, g_w1t);
    uint32_t* w2t; cudaGetSymbolAddress((void**)&w2t, g_w2t);
    uint32_t* w3t; cudaGetSymbolAddress((void**)&w3t, g_w3t);

    int wn4 = NEXP * FDIM * HDIM / 4;

    // launch index 3 (k_ffn1) is the one ncu captures
    k_cvt_all<<<(3 * wn4 + 255) / 256, 256>>>(
        (const float4*)w1, (uint4*)w1t,
        (const float4*)w2, (uint4*)w2t,
        (const float4*)w3, (uint4*)w3t, wn4);                                   // 0
    k_gate<<<T_TOK / 8, 256>>>(x, gw, (float4*)out);                            // 1
    k_scan_par<<<SCAN_B, SCAN_T>>>();                                           // 2
    k_ffn1<<<dim3(CAPP / 128, FDIM / 64, NEXP), 128, F1_SMEM>>>(x);             // 3 <- profiled
    k_ffn2<<<dim3(CAPP / 128, HDIM / 128, NEXP), 128, F2_SMEM>>>(out);          // 4
}